// round 12
// baseline (speedup 1.0000x reference)
#include <cuda_runtime.h>
#include <cuda_bf16.h>
#include <math.h>
#include <cstdint>

#define B_  2
#define S_  2048
#define D_  1024
#define H_  16
#define DH_ 64
#define M_  (B_ * S_)

// ---------------- scratch ----------------------------------------------------
__device__ __nv_bfloat16 g_xq[M_ * D_];
__device__ __nv_bfloat16 g_xk[M_ * D_];
__device__ __nv_bfloat16 g_xv[M_ * D_];
__device__ __nv_bfloat16 g_wq[D_ * D_];
__device__ __nv_bfloat16 g_wk[D_ * D_];
__device__ __nv_bfloat16 g_wv[D_ * D_];
__device__ __nv_bfloat16 g_Q[M_ * D_];
__device__ __nv_bfloat16 g_K[M_ * D_];
__device__ __nv_bfloat16 g_Vt[B_ * H_ * DH_ * S_];
__device__ float g_O[M_ * D_];
__device__ float g_kmask[M_];
__device__ float g_qmask[M_];

// ---------------- helpers ------------------------------------------------------
__device__ __forceinline__ unsigned pk2(float lo, float hi) {
    unsigned r;
    asm("cvt.rn.bf16x2.f32 %0, %1, %2;" : "=r"(r) : "f"(hi), "f"(lo));
    return r;
}
__device__ __forceinline__ float ex2(float x) {
    float y;
    asm("ex2.approx.f32 %0, %1;" : "=f"(y) : "f"(x));
    return y;
}
__device__ __forceinline__ void mmabf(float* c,
                                      unsigned a0, unsigned a1, unsigned a2, unsigned a3,
                                      unsigned b0, unsigned b1) {
    asm volatile(
        "mma.sync.aligned.m16n8k16.row.col.f32.bf16.bf16.f32 "
        "{%0,%1,%2,%3},{%4,%5,%6,%7},{%8,%9},{%0,%1,%2,%3};"
        : "+f"(c[0]), "+f"(c[1]), "+f"(c[2]), "+f"(c[3])
        : "r"(a0), "r"(a1), "r"(a2), "r"(a3), "r"(b0), "r"(b1));
}
__device__ __forceinline__ void cp16(void* smem, const void* gmem) {
    unsigned saddr = (unsigned)__cvta_generic_to_shared(smem);
    asm volatile("cp.async.cg.shared.global [%0], [%1], 16;" :: "r"(saddr), "l"(gmem));
}
#define CP_COMMIT() asm volatile("cp.async.commit_group;")
#define CP_WAIT(N)  asm volatile("cp.async.wait_group %0;" :: "n"(N))
__device__ __forceinline__ int sw4(int row, int c) { return c ^ ((row >> 1) & 3); }
__device__ __forceinline__ int sw8(int row, int c) { return c ^ (row & 7); }
__device__ __forceinline__ void ldm_x4(unsigned* r, const char* p) {
    uint32_t a = (uint32_t)__cvta_generic_to_shared(p);
    asm volatile("ldmatrix.sync.aligned.m8n8.x4.shared.b16 {%0,%1,%2,%3}, [%4];"
        : "=r"(r[0]), "=r"(r[1]), "=r"(r[2]), "=r"(r[3]) : "r"(a));
}

// ---------------- fp32 -> bf16 conversion + row masks ---------------------------
__global__ __launch_bounds__(256) void cvt_kernel(
    const float* __restrict__ q, const float* __restrict__ k, const float* __restrict__ v,
    const float* __restrict__ wq, const float* __restrict__ wk, const float* __restrict__ wv)
{
    __shared__ float rs[8];
    const int z = blockIdx.y;
    const float* src; __nv_bfloat16* dst; int n;
    if (z == 0)      { src = q;  dst = g_xq; n = M_ * D_; }
    else if (z == 1) { src = k;  dst = g_xk; n = M_ * D_; }
    else if (z == 2) { src = v;  dst = g_xv; n = M_ * D_; }
    else if (z == 3) { src = wq; dst = g_wq; n = D_ * D_; }
    else if (z == 4) { src = wk; dst = g_wk; n = D_ * D_; }
    else             { src = wv; dst = g_wv; n = D_ * D_; }

    const int tid = threadIdx.x;
    int base = (blockIdx.x * 256 + tid) * 8;
    if (base >= n) return;
    float4 a = *(const float4*)&src[base];
    float4 b = *(const float4*)&src[base + 4];
    uint4 o;
    o.x = pk2(a.x, a.y); o.y = pk2(a.z, a.w);
    o.z = pk2(b.x, b.y); o.w = pk2(b.z, b.w);
    *(uint4*)&dst[base] = o;

    if (z < 2) {
        float s = a.x + a.y + a.z + a.w + b.x + b.y + b.z + b.w;
        #pragma unroll
        for (int off = 16; off; off >>= 1) s += __shfl_xor_sync(0xffffffffu, s, off);
        if ((tid & 31) == 0) rs[tid >> 5] = s;
        __syncthreads();
        float* msk = (z == 0) ? g_qmask : g_kmask;
        if (tid == 0) {
            float t = rs[0] + rs[1] + rs[2] + rs[3];
            msk[blockIdx.x * 2] = (t != 0.0f) ? 1.0f : 0.0f;
        } else if (tid == 128) {
            float t = rs[4] + rs[5] + rs[6] + rs[7];
            msk[blockIdx.x * 2 + 1] = (t != 0.0f) ? 1.0f : 0.0f;
        }
    }
}

// ---------------- fused QKV projection (64x64 warp tile, 3-stage cp.async) ------
// CTA: 128x256 tile, 8 warps (2x4), warp 64x64. BK=32. K=1024 -> 32 iters.
#define NSTG 3
#define PA_BYTES (128 * 64)
#define PB_BYTES (256 * 64)
#define PSTG (PA_BYTES + PB_BYTES)    // 24576
__global__ __launch_bounds__(256, 1) void proj_kernel(
    const float* __restrict__ bq, const float* __restrict__ bk, const float* __restrict__ bv)
{
    extern __shared__ char psm[];

    const __nv_bfloat16* X; const __nv_bfloat16* W; __nv_bfloat16* out; const float* bias;
    if (blockIdx.z == 0)      { X = g_xq; W = g_wq; out = g_Q; bias = bq; }
    else if (blockIdx.z == 1) { X = g_xk; W = g_wk; out = g_K; bias = bk; }
    else                      { X = g_xv; W = g_wv; out = g_Q; bias = bv; }  // out unused z==2

    const int tid  = threadIdx.x;
    const int m0   = blockIdx.y * 128;
    const int n0   = blockIdx.x * 256;
    const int wid  = tid >> 5;
    const int lane = tid & 31;
    const int g    = lane >> 2;
    const int tig  = lane & 3;
    const int wm   = (wid >> 2) * 64;   // 0 or 64
    const int wn   = (wid & 3) * 64;    // 0..192
    const int sub  = lane >> 3;
    const int rin  = lane & 7;

    const int a_row = (sub & 1) * 8 + rin;
    const int a_co  = sub >> 1;
    const int b_row = (sub >> 1) * 8 + rin;
    const int b_co  = sub & 1;

    float acc[4][8][4];
    #pragma unroll
    for (int i = 0; i < 4; i++)
        #pragma unroll
        for (int j = 0; j < 8; j++)
            #pragma unroll
            for (int e = 0; e < 4; e++) acc[i][j][e] = 0.0f;

    auto load_stage = [&](int stage, int k0) {
        char* As = psm + stage * PSTG;
        char* Bs = As + PA_BYTES;
        #pragma unroll
        for (int lv = 0; lv < 2; lv++) {        // A: 128 rows x 4 chunks
            int idx = tid + lv * 256;
            int row = idx >> 2;
            int c   = idx & 3;
            cp16(As + row * 64 + sw4(row, c) * 16, &X[(size_t)(m0 + row) * D_ + k0 + c * 8]);
        }
        #pragma unroll
        for (int lv = 0; lv < 4; lv++) {        // B: 256 rows x 4 chunks
            int idx = tid + lv * 256;
            int row = idx >> 2;
            int c   = idx & 3;
            cp16(Bs + row * 64 + sw4(row, c) * 16, &W[(size_t)(n0 + row) * D_ + k0 + c * 8]);
        }
    };

    #pragma unroll
    for (int s = 0; s < NSTG - 1; s++) { load_stage(s, s * 32); CP_COMMIT(); }

    for (int it = 0; it < 32; it++) {
        CP_WAIT(NSTG - 2);
        __syncthreads();
        if (it + NSTG - 1 < 32) load_stage((it + NSTG - 1) % NSTG, (it + NSTG - 1) * 32);
        CP_COMMIT();

        char* As = psm + (it % NSTG) * PSTG;
        char* Bs = As + PA_BYTES;
        #pragma unroll
        for (int ks = 0; ks < 2; ks++) {
            unsigned af[4][4];
            #pragma unroll
            for (int mi = 0; mi < 4; mi++) {
                int r = wm + mi * 16 + a_row;
                ldm_x4(af[mi], As + r * 64 + sw4(r, 2 * ks + a_co) * 16);
            }
            #pragma unroll
            for (int p = 0; p < 4; p++) {
                unsigned bf[4];
                int r = wn + p * 16 + b_row;
                ldm_x4(bf, Bs + r * 64 + sw4(r, 2 * ks + b_co) * 16);
                #pragma unroll
                for (int mi = 0; mi < 4; mi++) {
                    mmabf(acc[mi][2 * p],     af[mi][0], af[mi][1], af[mi][2], af[mi][3], bf[0], bf[1]);
                    mmabf(acc[mi][2 * p + 1], af[mi][0], af[mi][1], af[mi][2], af[mi][3], bf[2], bf[3]);
                }
            }
        }
    }

    if (blockIdx.z != 2) {
        // Q/K: direct store
        #pragma unroll
        for (int mi = 0; mi < 4; mi++) {
            int r0 = m0 + wm + mi * 16 + g;
            #pragma unroll
            for (int ni = 0; ni < 8; ni++) {
                int cc = n0 + wn + ni * 8 + 2 * tig;
                float bb0 = bias[cc], bb1 = bias[cc + 1];
                *(unsigned*)&out[(size_t)r0 * D_ + cc] =
                    pk2(fmaxf(acc[mi][ni][0] + bb0, 0.0f), fmaxf(acc[mi][ni][1] + bb1, 0.0f));
                *(unsigned*)&out[(size_t)(r0 + 8) * D_ + cc] =
                    pk2(fmaxf(acc[mi][ni][2] + bb0, 0.0f), fmaxf(acc[mi][ni][3] + bb1, 0.0f));
            }
        }
    } else {
        // V: transpose to g_Vt in two 128-column half-passes
        unsigned* stage = (unsigned*)psm;   // 128 rows x 68-word pitch (34.8 KB)
        const int bb  = m0 >> 11;
        const int s0l = m0 & 2047;
        #pragma unroll 1
        for (int hh = 0; hh < 2; hh++) {
            __syncthreads();
            if ((wn >> 7) == hh) {
                int wnl = wn & 127;         // 0 or 64
                #pragma unroll
                for (int mi = 0; mi < 4; mi++) {
                    int rl = wm + mi * 16 + g;
                    #pragma unroll
                    for (int ni = 0; ni < 8; ni++) {
                        int ccl = wnl + ni * 8 + 2 * tig;
                        int gc  = n0 + hh * 128 + ccl;
                        float bb0 = bias[gc], bb1 = bias[gc + 1];
                        stage[rl * 68 + ccl / 2] =
                            pk2(fmaxf(acc[mi][ni][0] + bb0, 0.0f), fmaxf(acc[mi][ni][1] + bb1, 0.0f));
                        stage[(rl + 8) * 68 + ccl / 2] =
                            pk2(fmaxf(acc[mi][ni][2] + bb0, 0.0f), fmaxf(acc[mi][ni][3] + bb1, 0.0f));
                    }
                }
            }
            __syncthreads();
            #pragma unroll
            for (int i = 0; i < 8; i++) {
                int idx = tid + i * 256;
                int c   = idx & 127;
                int rg  = idx >> 7;
                int r0r = rg * 8;
                int gc  = n0 + hh * 128 + c;
                int h   = gc >> 6;
                int d   = gc & 63;
                unsigned sel = (c & 1) ? 0x7632u : 0x5410u;
                uint4 o;
                unsigned* po = (unsigned*)&o;
                #pragma unroll
                for (int j = 0; j < 4; j++) {
                    unsigned w0 = stage[(r0r + 2 * j)     * 68 + (c >> 1)];
                    unsigned w1 = stage[(r0r + 2 * j + 1) * 68 + (c >> 1)];
                    asm("prmt.b32 %0, %1, %2, %3;" : "=r"(po[j]) : "r"(w0), "r"(w1), "r"(sel));
                }
                *(uint4*)&g_Vt[(size_t)((bb * H_ + h) * DH_ + d) * S_ + s0l + r0r] = o;
            }
        }
    }
}

// ---------------- causal flash attention (paired q-tiles, uniform blocks) -------
#define AKQ 16384
#define AKV (AKQ + 4 * 8192)
#define AKM (AKV + 4 * 8192)
#define ATTN_SMEM (AKM + 4 * 256)
#define CS 0.1803368801f   // 0.125 * log2(e)
__global__ __launch_bounds__(256) void attn_kernel()
{
    extern __shared__ char sm[];
    char*  qp  = sm;
    char*  Kst = sm + AKQ;
    char*  Vst = sm + AKV;
    float* kms = (float*)(sm + AKM);

    const int h    = blockIdx.y;
    const int b    = blockIdx.z;
    const int tid  = threadIdx.x;
    const int lane = tid & 31;
    const int wid  = tid >> 5;
    const int g    = lane >> 2;
    const int tig  = lane & 3;
    const int rb   = wid * 16;
    const int sub  = lane >> 3;
    const int rin  = lane & 7;

    const int a_row = (sub & 1) * 8 + rin;
    const int a_co  = sub >> 1;
    const int b_row = (sub >> 1) * 8 + rin;
    const int b_co  = sub & 1;

    const __nv_bfloat16* Vtg = g_Vt + (size_t)(b * H_ + h) * DH_ * S_;

    auto ld_tile = [&](int t) {
        char* Ks = Kst + (t & 3) * 8192;
        char* Vs = Vst + (t & 3) * 8192;
        int sn = t * 64;
        #pragma unroll
        for (int lv = 0; lv < 2; lv++) {
            int idx = tid + lv * 256;
            int r = idx >> 3;
            int c = idx & 7;
            cp16(Ks + r * 128 + sw8(r, c) * 16,
                 &g_K[(size_t)(b * S_ + sn + r) * D_ + h * DH_ + c * 8]);
            cp16(Vs + r * 128 + sw8(r, c) * 16, &Vtg[(size_t)r * S_ + sn + c * 8]);
        }
        if (tid < 16) cp16(&kms[(t & 3) * 64 + tid * 4], &g_kmask[b * S_ + sn + tid * 4]);
    };

    #pragma unroll 1
    for (int half = 0; half < 2; half++) {
        const int qt  = half ? (int)blockIdx.x : (int)(15 - blockIdx.x);
        const int qb0 = qt * 128;
        const int ntile = (qb0 >> 6) + 2;

        __syncthreads();

        #pragma unroll
        for (int lv = 0; lv < 4; lv++) {
            int idx = tid + lv * 256;
            int r = idx >> 3;
            int c = idx & 7;
            cp16(qp + r * 128 + sw8(r, c) * 16,
                 &g_Q[(size_t)(b * S_ + qb0 + r) * D_ + h * DH_ + c * 8]);
        }
        CP_COMMIT();
        ld_tile(0); CP_COMMIT();
        ld_tile(1); CP_COMMIT();

        CP_WAIT(1);
        __syncthreads();

        unsigned qa[4][4];
        #pragma unroll
        for (int ks = 0; ks < 4; ks++) {
            int r = rb + a_row;
            ldm_x4(qa[ks], qp + r * 128 + sw8(r, 2 * ks + a_co) * 16);
        }

        float oacc[8][4];
        #pragma unroll
        for (int ni = 0; ni < 8; ni++)
            #pragma unroll
            for (int e = 0; e < 4; e++) oacc[ni][e] = 0.0f;

        const int row0 = qb0 + rb + g;
        const int row1 = row0 + 8;
        const int rmax = qb0 + rb + 15;

        float mrow0, mrow1, lrow0, lrow1;
        unsigned pp[8][2];

        // prologue: S(0) + softmax(0)
        {
            char*  Ksm = Kst;
            float* kmc = kms;
            float scn[8][4];
            #pragma unroll
            for (int ni = 0; ni < 8; ni++)
                #pragma unroll
                for (int e = 0; e < 4; e++) scn[ni][e] = 0.0f;
            #pragma unroll
            for (int ks = 0; ks < 4; ks++) {
                #pragma unroll
                for (int p = 0; p < 4; p++) {
                    unsigned kf[4];
                    int r = p * 16 + b_row;
                    ldm_x4(kf, Ksm + r * 128 + sw8(r, 2 * ks + b_co) * 16);
                    mmabf(scn[2 * p],     qa[ks][0], qa[ks][1], qa[ks][2], qa[ks][3], kf[0], kf[1]);
                    mmabf(scn[2 * p + 1], qa[ks][0], qa[ks][1], qa[ks][2], qa[ks][3], kf[2], kf[3]);
                }
            }
            float kv0 = kmc[lane], kv1 = kmc[lane + 32];
            bool okk = (kv0 != 0.0f) && (kv1 != 0.0f);
            bool allvalid = (__ballot_sync(0xffffffffu, okk) == 0xffffffffu);
            bool interior = (63 <= qb0 + rb);
            float vm0 = -1e30f, vm1 = -1e30f;
            if (interior && allvalid) {
                #pragma unroll
                for (int ni = 0; ni < 8; ni++) {
                    vm0 = fmaxf(vm0, fmaxf(scn[ni][0], scn[ni][1]));
                    vm1 = fmaxf(vm1, fmaxf(scn[ni][2], scn[ni][3]));
                }
            } else {
                #pragma unroll
                for (int ni = 0; ni < 8; ni++) {
                    #pragma unroll
                    for (int e = 0; e < 2; e++) {
                        int cl = ni * 8 + 2 * tig + e;
                        bool km = (kmc[cl] != 0.0f);
                        float v0 = (cl > row0 || !km) ? -1e30f : scn[ni][e];
                        float v1 = (cl > row1 || !km) ? -1e30f : scn[ni][2 + e];
                        scn[ni][e] = v0; scn[ni][2 + e] = v1;
                        vm0 = fmaxf(vm0, v0); vm1 = fmaxf(vm1, v1);
                    }
                }
            }
            vm0 = fmaxf(vm0, __shfl_xor_sync(0xffffffffu, vm0, 1));
            vm0 = fmaxf(vm0, __shfl_xor_sync(0xffffffffu, vm0, 2));
            vm1 = fmaxf(vm1, __shfl_xor_sync(0xffffffffu, vm1, 1));
            vm1 = fmaxf(vm1, __shfl_xor_sync(0xffffffffu, vm1, 2));
            mrow0 = vm0 * CS;
            mrow1 = vm1 * CS;
            float ps0 = 0.0f, ps1 = 0.0f;
            #pragma unroll
            for (int ni = 0; ni < 8; ni++) {
                float p00 = ex2(fmaf(scn[ni][0], CS, -mrow0));
                float p01 = ex2(fmaf(scn[ni][1], CS, -mrow0));
                float p10 = ex2(fmaf(scn[ni][2], CS, -mrow1));
                float p11 = ex2(fmaf(scn[ni][3], CS, -mrow1));
                ps0 += p00 + p01; ps1 += p10 + p11;
                pp[ni][0] = pk2(p00, p01);
                pp[ni][1] = pk2(p10, p11);
            }
            ps0 += __shfl_xor_sync(0xffffffffu, ps0, 1);
            ps0 += __shfl_xor_sync(0xffffffffu, ps0, 2);
            ps1 += __shfl_xor_sync(0xffffffffu, ps1, 1);
            ps1 += __shfl_xor_sync(0xffffffffu, ps1, 2);
            lrow0 = ps0; lrow1 = ps1;
        }

        for (int kt = 0; kt < ntile; kt++) {
            if (kt + 2 < ntile) ld_tile(kt + 2);
            CP_COMMIT();
            CP_WAIT(1);
            __syncthreads();

            if (kt * 64 > rmax) continue;
            char* Vsm = Vst + (kt & 3) * 8192;
            bool activeN = (kt + 1 < ntile) && ((kt + 1) * 64 <= rmax);

            if (activeN) {
                char*  Ksm = Kst + ((kt + 1) & 3) * 8192;
                float* kmc = kms + ((kt + 1) & 3) * 64;
                const int sn0 = (kt + 1) * 64;

                float scn[8][4];
                #pragma unroll
                for (int ni = 0; ni < 8; ni++)
                    #pragma unroll
                    for (int e = 0; e < 4; e++) scn[ni][e] = 0.0f;
                #pragma unroll
                for (int ks = 0; ks < 4; ks++) {
                    #pragma unroll
                    for (int p = 0; p < 4; p++) {
                        unsigned kf[4];
                        int r = p * 16 + b_row;
                        ldm_x4(kf, Ksm + r * 128 + sw8(r, 2 * ks + b_co) * 16);
                        mmabf(scn[2 * p],     qa[ks][0], qa[ks][1], qa[ks][2], qa[ks][3], kf[0], kf[1]);
                        mmabf(scn[2 * p + 1], qa[ks][0], qa[ks][1], qa[ks][2], qa[ks][3], kf[2], kf[3]);
                    }
                }

                float kv0 = kmc[lane], kv1 = kmc[lane + 32];
                bool okk = (kv0 != 0.0f) && (kv1 != 0.0f);
                bool allvalid = (__ballot_sync(0xffffffffu, okk) == 0xffffffffu);
                bool interior = (sn0 + 63 <= qb0 + rb);
                float vm0 = -1e30f, vm1 = -1e30f;
                if (interior && allvalid) {
                    #pragma unroll
                    for (int ni = 0; ni < 8; ni++) {
                        vm0 = fmaxf(vm0, fmaxf(scn[ni][0], scn[ni][1]));
                        vm1 = fmaxf(vm1, fmaxf(scn[ni][2], scn[ni][3]));
                    }
                } else {
                    #pragma unroll
                    for (int ni = 0; ni < 8; ni++) {
                        #pragma unroll
                        for (int e = 0; e < 2; e++) {
                            int cl = ni * 8 + 2 * tig + e;
                            int sg = sn0 + cl;
                            bool km = (kmc[cl] != 0.0f);
                            float v0 = (sg > row0 || !km) ? -1e30f : scn[ni][e];
                            float v1 = (sg > row1 || !km) ? -1e30f : scn[ni][2 + e];
                            scn[ni][e] = v0; scn[ni][2 + e] = v1;
                            vm0 = fmaxf(vm0, v0); vm1 = fmaxf(vm1, v1);
                        }
                    }
                }
                vm0 = fmaxf(vm0, __shfl_xor_sync(0xffffffffu, vm0, 1));
                vm0 = fmaxf(vm0, __shfl_xor_sync(0xffffffffu, vm0, 2));
                vm1 = fmaxf(vm1, __shfl_xor_sync(0xffffffffu, vm1, 1));
                vm1 = fmaxf(vm1, __shfl_xor_sync(0xffffffffu, vm1, 2));
                float mn0 = fmaxf(mrow0, vm0 * CS);
                float mn1 = fmaxf(mrow1, vm1 * CS);

                unsigned ppn[8][2];
                float ps0 = 0.0f, ps1 = 0.0f;
                #pragma unroll
                for (int ni = 0; ni < 8; ni++) {
                    float p00 = ex2(fmaf(scn[ni][0], CS, -mn0));
                    float p01 = ex2(fmaf(scn[ni][1], CS, -mn0));
                    float p10 = ex2(fmaf(scn[ni][2], CS, -mn1));
                    float p11 = ex2(fmaf(scn[ni][3], CS, -mn1));
                    ps0 += p00 + p01; ps1 += p10 + p11;
                    ppn[ni][0] = pk2(p00, p01);
                    ppn[ni][1] = pk2(p10, p11);
                }
                ps0 += __shfl_xor_sync(0xffffffffu, ps0, 1);
                ps0 += __shfl_xor_sync(0xffffffffu, ps0, 2);
                ps1 += __shfl_xor_sync(0xffffffffu, ps1, 1);
                ps1 += __shfl_xor_sync(0xffffffffu, ps1, 2);

                #pragma unroll
                for (int ks = 0; ks < 4; ks++) {
                    unsigned pa0 = pp[2 * ks][0];
                    unsigned pa1 = pp[2 * ks][1];
                    unsigned pa2 = pp[2 * ks + 1][0];
                    unsigned pa3 = pp[2 * ks + 1][1];
                    #pragma unroll
                    for (int p = 0; p < 4; p++) {
                        unsigned vf[4];
                        int r = p * 16 + b_row;
                        ldm_x4(vf, Vsm + r * 128 + sw8(r, 2 * ks + b_co) * 16);
                        mmabf(oacc[2 * p],     pa0, pa1, pa2, pa3, vf[0], vf[1]);
                        mmabf(oacc[2 * p + 1], pa0, pa1, pa2, pa3, vf[2], vf[3]);
                    }
                }

                float al0 = ex2(mrow0 - mn0), al1 = ex2(mrow1 - mn1);
                lrow0 = lrow0 * al0 + ps0;
                lrow1 = lrow1 * al1 + ps1;
                mrow0 = mn0; mrow1 = mn1;
                #pragma unroll
                for (int ni = 0; ni < 8; ni++) {
                    oacc[ni][0] *= al0; oacc[ni][1] *= al0;
                    oacc[ni][2] *= al1; oacc[ni][3] *= al1;
                    pp[ni][0] = ppn[ni][0];
                    pp[ni][1] = ppn[ni][1];
                }
            } else {
                #pragma unroll
                for (int ks = 0; ks < 4; ks++) {
                    unsigned pa0 = pp[2 * ks][0];
                    unsigned pa1 = pp[2 * ks][1];
                    unsigned pa2 = pp[2 * ks + 1][0];
                    unsigned pa3 = pp[2 * ks + 1][1];
                    #pragma unroll
                    for (int p = 0; p < 4; p++) {
                        unsigned vf[4];
                        int r = p * 16 + b_row;
                        ldm_x4(vf, Vsm + r * 128 + sw8(r, 2 * ks + b_co) * 16);
                        mmabf(oacc[2 * p],     pa0, pa1, pa2, pa3, vf[0], vf[1]);
                        mmabf(oacc[2 * p + 1], pa0, pa1, pa2, pa3, vf[2], vf[3]);
                    }
                }
            }
        }

        float qm0 = g_qmask[b * S_ + row0];
        float qm1 = g_qmask[b * S_ + row1];
        float inv0 = qm0 / lrow0;
        float inv1 = qm1 / lrow1;
        #pragma unroll
        for (int ni = 0; ni < 8; ni++) {
            int cc = h * DH_ + ni * 8 + 2 * tig;
            float2 v0, v1;
            v0.x = oacc[ni][0] * inv0; v0.y = oacc[ni][1] * inv0;
            v1.x = oacc[ni][2] * inv1; v1.y = oacc[ni][3] * inv1;
            *(float2*)&g_O[(size_t)(b * S_ + row0) * D_ + cc] = v0;
            *(float2*)&g_O[(size_t)(b * S_ + row1) * D_ + cc] = v1;
        }
    }
}

// ---------------- residual + layernorm ------------------------------------------
__global__ __launch_bounds__(256) void ln_kernel(
    const float* __restrict__ qin, const float* __restrict__ gamma,
    const float* __restrict__ beta, float* __restrict__ out)
{
    __shared__ float red[8];
    __shared__ float red2[8];
    const int row = blockIdx.x;
    const int tid = threadIdx.x;
    size_t base = (size_t)row * D_ + tid * 4;

    float4 o = *(const float4*)&g_O[base];
    float4 q = *(const float4*)&qin[base];
    float x0 = o.x + q.x, x1 = o.y + q.y, x2 = o.z + q.z, x3 = o.w + q.w;

    float s = x0 + x1 + x2 + x3;
    #pragma unroll
    for (int off = 16; off; off >>= 1) s += __shfl_xor_sync(0xffffffffu, s, off);
    if ((tid & 31) == 0) red[tid >> 5] = s;
    __syncthreads();
    float tot = red[0] + red[1] + red[2] + red[3] + red[4] + red[5] + red[6] + red[7];
    float mean = tot * (1.0f / 1024.0f);

    float d0 = x0 - mean, d1 = x1 - mean, d2 = x2 - mean, d3 = x3 - mean;
    float sq = d0 * d0 + d1 * d1 + d2 * d2 + d3 * d3;
    #pragma unroll
    for (int off = 16; off; off >>= 1) sq += __shfl_xor_sync(0xffffffffu, sq, off);
    if ((tid & 31) == 0) red2[tid >> 5] = sq;
    __syncthreads();
    float ssq = red2[0] + red2[1] + red2[2] + red2[3] + red2[4] + red2[5] + red2[6] + red2[7];
    float stdv = sqrtf(ssq / 1023.0f);
    float inv = 1.0f / (stdv + 1e-8f);

    float4 gg = *(const float4*)&gamma[tid * 4];
    float4 be = *(const float4*)&beta[tid * 4];
    float4 y;
    y.x = gg.x * d0 * inv + be.x;
    y.y = gg.y * d1 * inv + be.y;
    y.z = gg.z * d2 * inv + be.z;
    y.w = gg.w * d3 * inv + be.w;
    *(float4*)&out[base] = y;
}

// ---------------- launch -----------------------------------------------------------
extern "C" void kernel_launch(void* const* d_in, const int* in_sizes, int n_in,
                              void* d_out, int out_size)
{
    const float* queries = (const float*)d_in[0];
    const float* keys    = (const float*)d_in[1];
    const float* values  = (const float*)d_in[2];
    const float* Wq      = (const float*)d_in[3];
    const float* bq      = (const float*)d_in[4];
    const float* Wk      = (const float*)d_in[5];
    const float* bk      = (const float*)d_in[6];
    const float* Wv      = (const float*)d_in[7];
    const float* bv      = (const float*)d_in[8];
    const float* gamma   = (const float*)d_in[9];
    const float* beta    = (const float*)d_in[10];
    float* out = (float*)d_out;

    const int proj_smem = NSTG * PSTG;   // 73728 B
    cudaFuncSetAttribute(proj_kernel, cudaFuncAttributeMaxDynamicSharedMemorySize, proj_smem);
    cudaFuncSetAttribute(attn_kernel, cudaFuncAttributeMaxDynamicSharedMemorySize, ATTN_SMEM);

    cvt_kernel<<<dim3(2048, 6), 256>>>(queries, keys, values, Wq, Wk, Wv);
    proj_kernel<<<dim3(4, 32, 3), 256, proj_smem>>>(bq, bk, bv);
    attn_kernel<<<dim3(8, 16, 2), 256, ATTN_SMEM>>>();
    ln_kernel<<<M_, 256>>>(queries, gamma, beta, out);
}

// round 13
// speedup vs baseline: 1.1146x; 1.1146x over previous
#include <cuda_runtime.h>
#include <cuda_bf16.h>
#include <math.h>
#include <cstdint>

#define B_  2
#define S_  2048
#define D_  1024
#define H_  16
#define DH_ 64
#define M_  (B_ * S_)

// ---------------- scratch ----------------------------------------------------
__device__ __nv_bfloat16 g_xq[M_ * D_];
__device__ __nv_bfloat16 g_xk[M_ * D_];
__device__ __nv_bfloat16 g_xv[M_ * D_];
__device__ __nv_bfloat16 g_wq[D_ * D_];
__device__ __nv_bfloat16 g_wk[D_ * D_];
__device__ __nv_bfloat16 g_wv[D_ * D_];
__device__ __nv_bfloat16 g_Q[M_ * D_];
__device__ __nv_bfloat16 g_K[M_ * D_];
__device__ __nv_bfloat16 g_Vt[B_ * H_ * DH_ * S_];
__device__ float g_O[M_ * D_];
__device__ float g_kmask[M_];
__device__ float g_qmask[M_];

// ---------------- helpers ------------------------------------------------------
__device__ __forceinline__ unsigned pk2(float lo, float hi) {
    unsigned r;
    asm("cvt.rn.bf16x2.f32 %0, %1, %2;" : "=r"(r) : "f"(hi), "f"(lo));
    return r;
}
__device__ __forceinline__ float ex2(float x) {
    float y;
    asm("ex2.approx.f32 %0, %1;" : "=f"(y) : "f"(x));
    return y;
}
__device__ __forceinline__ void mmabf(float* c,
                                      unsigned a0, unsigned a1, unsigned a2, unsigned a3,
                                      unsigned b0, unsigned b1) {
    asm volatile(
        "mma.sync.aligned.m16n8k16.row.col.f32.bf16.bf16.f32 "
        "{%0,%1,%2,%3},{%4,%5,%6,%7},{%8,%9},{%0,%1,%2,%3};"
        : "+f"(c[0]), "+f"(c[1]), "+f"(c[2]), "+f"(c[3])
        : "r"(a0), "r"(a1), "r"(a2), "r"(a3), "r"(b0), "r"(b1));
}
__device__ __forceinline__ void cp16(void* smem, const void* gmem) {
    unsigned saddr = (unsigned)__cvta_generic_to_shared(smem);
    asm volatile("cp.async.cg.shared.global [%0], [%1], 16;" :: "r"(saddr), "l"(gmem));
}
#define CP_COMMIT() asm volatile("cp.async.commit_group;")
#define CP_WAIT(N)  asm volatile("cp.async.wait_group %0;" :: "n"(N))
__device__ __forceinline__ int sw8(int row, int c) { return c ^ (row & 7); }
__device__ __forceinline__ void ldm_x4(unsigned* r, const char* p) {
    uint32_t a = (uint32_t)__cvta_generic_to_shared(p);
    asm volatile("ldmatrix.sync.aligned.m8n8.x4.shared.b16 {%0,%1,%2,%3}, [%4];"
        : "=r"(r[0]), "=r"(r[1]), "=r"(r[2]), "=r"(r[3]) : "r"(a));
}

// ---------------- fp32 -> bf16 conversion + row masks ---------------------------
__global__ __launch_bounds__(256) void cvt_kernel(
    const float* __restrict__ q, const float* __restrict__ k, const float* __restrict__ v,
    const float* __restrict__ wq, const float* __restrict__ wk, const float* __restrict__ wv)
{
    __shared__ float rs[8];
    const int z = blockIdx.y;
    const float* src; __nv_bfloat16* dst; int n;
    if (z == 0)      { src = q;  dst = g_xq; n = M_ * D_; }
    else if (z == 1) { src = k;  dst = g_xk; n = M_ * D_; }
    else if (z == 2) { src = v;  dst = g_xv; n = M_ * D_; }
    else if (z == 3) { src = wq; dst = g_wq; n = D_ * D_; }
    else if (z == 4) { src = wk; dst = g_wk; n = D_ * D_; }
    else             { src = wv; dst = g_wv; n = D_ * D_; }

    const int tid = threadIdx.x;
    int base = (blockIdx.x * 256 + tid) * 8;
    if (base >= n) return;
    float4 a = *(const float4*)&src[base];
    float4 b = *(const float4*)&src[base + 4];
    uint4 o;
    o.x = pk2(a.x, a.y); o.y = pk2(a.z, a.w);
    o.z = pk2(b.x, b.y); o.w = pk2(b.z, b.w);
    *(uint4*)&dst[base] = o;

    if (z < 2) {
        float s = a.x + a.y + a.z + a.w + b.x + b.y + b.z + b.w;
        #pragma unroll
        for (int off = 16; off; off >>= 1) s += __shfl_xor_sync(0xffffffffu, s, off);
        if ((tid & 31) == 0) rs[tid >> 5] = s;
        __syncthreads();
        float* msk = (z == 0) ? g_qmask : g_kmask;
        if (tid == 0) {
            float t = rs[0] + rs[1] + rs[2] + rs[3];
            msk[blockIdx.x * 2] = (t != 0.0f) ? 1.0f : 0.0f;
        } else if (tid == 128) {
            float t = rs[4] + rs[5] + rs[6] + rs[7];
            msk[blockIdx.x * 2 + 1] = (t != 0.0f) ? 1.0f : 0.0f;
        }
    }
}

// ---------------- fused QKV projection (64x32 warp tile, BK=64, 3-stage) --------
// CTA: 128x128 tile, 8 warps (2x4), warp 64x32. BK=64 -> 16 iterations.
// Stage = A 128x128B + B 128x128B = 32 KB. 3 stages = 96 KB.
#define NSTG 3
#define PA_BYTES (128 * 128)
#define PSTG (2 * PA_BYTES)           // 32768
__global__ __launch_bounds__(256) void proj_kernel(
    const float* __restrict__ bq, const float* __restrict__ bk, const float* __restrict__ bv)
{
    extern __shared__ char psm[];

    const __nv_bfloat16* X; const __nv_bfloat16* W; __nv_bfloat16* out; const float* bias;
    if (blockIdx.z == 0)      { X = g_xq; W = g_wq; out = g_Q; bias = bq; }
    else if (blockIdx.z == 1) { X = g_xk; W = g_wk; out = g_K; bias = bk; }
    else                      { X = g_xv; W = g_wv; out = g_Q; bias = bv; }  // out unused z==2

    const int tid  = threadIdx.x;
    const int m0   = blockIdx.y * 128;
    const int n0   = blockIdx.x * 128;
    const int wid  = tid >> 5;
    const int lane = tid & 31;
    const int g    = lane >> 2;
    const int tig  = lane & 3;
    const int wm   = (wid >> 2) * 64;
    const int wn   = (wid & 3) * 32;
    const int sub  = lane >> 3;
    const int rin  = lane & 7;

    const int a_row = (sub & 1) * 8 + rin;
    const int a_co  = sub >> 1;
    const int b_row = (sub >> 1) * 8 + rin;
    const int b_co  = sub & 1;

    float acc[4][4][4];
    #pragma unroll
    for (int i = 0; i < 4; i++)
        #pragma unroll
        for (int j = 0; j < 4; j++)
            #pragma unroll
            for (int e = 0; e < 4; e++) acc[i][j][e] = 0.0f;

    auto load_stage = [&](int stage, int k0) {
        char* As = psm + stage * PSTG;
        char* Bs = As + PA_BYTES;
        #pragma unroll
        for (int lv = 0; lv < 4; lv++) {      // A: 128 rows x 8 chunks
            int idx = tid + lv * 256;
            int row = idx >> 3;
            int c   = idx & 7;
            cp16(As + row * 128 + sw8(row, c) * 16, &X[(size_t)(m0 + row) * D_ + k0 + c * 8]);
        }
        #pragma unroll
        for (int lv = 0; lv < 4; lv++) {      // B: 128 rows x 8 chunks
            int idx = tid + lv * 256;
            int row = idx >> 3;
            int c   = idx & 7;
            cp16(Bs + row * 128 + sw8(row, c) * 16, &W[(size_t)(n0 + row) * D_ + k0 + c * 8]);
        }
    };

    #pragma unroll
    for (int s = 0; s < NSTG - 1; s++) { load_stage(s, s * 64); CP_COMMIT(); }

    for (int it = 0; it < 16; it++) {
        CP_WAIT(NSTG - 2);
        __syncthreads();
        if (it + NSTG - 1 < 16) load_stage((it + NSTG - 1) % NSTG, (it + NSTG - 1) * 64);
        CP_COMMIT();

        char* As = psm + (it % NSTG) * PSTG;
        char* Bs = As + PA_BYTES;
        #pragma unroll
        for (int ks = 0; ks < 4; ks++) {
            unsigned af[4][4], bf[2][4];
            #pragma unroll
            for (int mi = 0; mi < 4; mi++) {
                int r = wm + mi * 16 + a_row;
                ldm_x4(af[mi], As + r * 128 + sw8(r, 2 * ks + a_co) * 16);
            }
            #pragma unroll
            for (int p = 0; p < 2; p++) {
                int r = wn + p * 16 + b_row;
                ldm_x4(bf[p], Bs + r * 128 + sw8(r, 2 * ks + b_co) * 16);
            }
            #pragma unroll
            for (int mi = 0; mi < 4; mi++)
                #pragma unroll
                for (int ni = 0; ni < 4; ni++)
                    mmabf(acc[mi][ni], af[mi][0], af[mi][1], af[mi][2], af[mi][3],
                          bf[ni >> 1][(ni & 1) * 2], bf[ni >> 1][(ni & 1) * 2 + 1]);
        }
    }

    if (blockIdx.z != 2) {
        #pragma unroll
        for (int mi = 0; mi < 4; mi++) {
            int r0 = m0 + wm + mi * 16 + g;
            #pragma unroll
            for (int ni = 0; ni < 4; ni++) {
                int cc = n0 + wn + ni * 8 + 2 * tig;
                float bb0 = bias[cc], bb1 = bias[cc + 1];
                *(unsigned*)&out[(size_t)r0 * D_ + cc] =
                    pk2(fmaxf(acc[mi][ni][0] + bb0, 0.0f), fmaxf(acc[mi][ni][1] + bb1, 0.0f));
                *(unsigned*)&out[(size_t)(r0 + 8) * D_ + cc] =
                    pk2(fmaxf(acc[mi][ni][2] + bb0, 0.0f), fmaxf(acc[mi][ni][3] + bb1, 0.0f));
            }
        }
    } else {
        __syncthreads();
        unsigned* stage = (unsigned*)psm;   // 128 rows x 68-word pitch
        #pragma unroll
        for (int mi = 0; mi < 4; mi++) {
            int rl = wm + mi * 16 + g;
            #pragma unroll
            for (int ni = 0; ni < 4; ni++) {
                int ccl = wn + ni * 8 + 2 * tig;
                float bb0 = bias[n0 + ccl], bb1 = bias[n0 + ccl + 1];
                stage[rl * 68 + ccl / 2] =
                    pk2(fmaxf(acc[mi][ni][0] + bb0, 0.0f), fmaxf(acc[mi][ni][1] + bb1, 0.0f));
                stage[(rl + 8) * 68 + ccl / 2] =
                    pk2(fmaxf(acc[mi][ni][2] + bb0, 0.0f), fmaxf(acc[mi][ni][3] + bb1, 0.0f));
            }
        }
        __syncthreads();
        const int bb = m0 >> 11;
        const int s0 = m0 & 2047;
        #pragma unroll
        for (int i = 0; i < 8; i++) {
            int idx = tid + i * 256;
            int c   = idx & 127;
            int rg  = idx >> 7;
            int r0r = rg * 8;
            int h   = (n0 + c) >> 6;
            int d   = (n0 + c) & 63;
            unsigned sel = (c & 1) ? 0x7632u : 0x5410u;
            uint4 o;
            unsigned* po = (unsigned*)&o;
            #pragma unroll
            for (int j = 0; j < 4; j++) {
                unsigned w0 = stage[(r0r + 2 * j)     * 68 + (c >> 1)];
                unsigned w1 = stage[(r0r + 2 * j + 1) * 68 + (c >> 1)];
                asm("prmt.b32 %0, %1, %2, %3;" : "=r"(po[j]) : "r"(w0), "r"(w1), "r"(sel));
            }
            *(uint4*)&g_Vt[(size_t)((bb * H_ + h) * DH_ + d) * S_ + s0 + r0r] = o;
        }
    }
}

// ---------------- causal flash attention (paired q-tiles, uniform blocks) -------
#define AKQ 16384
#define AKV (AKQ + 4 * 8192)
#define AKM (AKV + 4 * 8192)
#define ATTN_SMEM (AKM + 4 * 256)
#define CS 0.1803368801f   // 0.125 * log2(e)
__global__ __launch_bounds__(256) void attn_kernel()
{
    extern __shared__ char sm[];
    char*  qp  = sm;
    char*  Kst = sm + AKQ;
    char*  Vst = sm + AKV;
    float* kms = (float*)(sm + AKM);

    const int h    = blockIdx.y;
    const int b    = blockIdx.z;
    const int tid  = threadIdx.x;
    const int lane = tid & 31;
    const int wid  = tid >> 5;
    const int g    = lane >> 2;
    const int tig  = lane & 3;
    const int rb   = wid * 16;
    const int sub  = lane >> 3;
    const int rin  = lane & 7;

    const int a_row = (sub & 1) * 8 + rin;
    const int a_co  = sub >> 1;
    const int b_row = (sub >> 1) * 8 + rin;
    const int b_co  = sub & 1;

    const __nv_bfloat16* Vtg = g_Vt + (size_t)(b * H_ + h) * DH_ * S_;

    auto ld_tile = [&](int t) {
        char* Ks = Kst + (t & 3) * 8192;
        char* Vs = Vst + (t & 3) * 8192;
        int sn = t * 64;
        #pragma unroll
        for (int lv = 0; lv < 2; lv++) {
            int idx = tid + lv * 256;
            int r = idx >> 3;
            int c = idx & 7;
            cp16(Ks + r * 128 + sw8(r, c) * 16,
                 &g_K[(size_t)(b * S_ + sn + r) * D_ + h * DH_ + c * 8]);
            cp16(Vs + r * 128 + sw8(r, c) * 16, &Vtg[(size_t)r * S_ + sn + c * 8]);
        }
        if (tid < 16) cp16(&kms[(t & 3) * 64 + tid * 4], &g_kmask[b * S_ + sn + tid * 4]);
    };

    #pragma unroll 1
    for (int half = 0; half < 2; half++) {
        const int qt  = half ? (int)blockIdx.x : (int)(15 - blockIdx.x);
        const int qb0 = qt * 128;
        const int ntile = (qb0 >> 6) + 2;

        __syncthreads();

        #pragma unroll
        for (int lv = 0; lv < 4; lv++) {
            int idx = tid + lv * 256;
            int r = idx >> 3;
            int c = idx & 7;
            cp16(qp + r * 128 + sw8(r, c) * 16,
                 &g_Q[(size_t)(b * S_ + qb0 + r) * D_ + h * DH_ + c * 8]);
        }
        CP_COMMIT();
        ld_tile(0); CP_COMMIT();
        ld_tile(1); CP_COMMIT();

        CP_WAIT(1);
        __syncthreads();

        unsigned qa[4][4];
        #pragma unroll
        for (int ks = 0; ks < 4; ks++) {
            int r = rb + a_row;
            ldm_x4(qa[ks], qp + r * 128 + sw8(r, 2 * ks + a_co) * 16);
        }

        float oacc[8][4];
        #pragma unroll
        for (int ni = 0; ni < 8; ni++)
            #pragma unroll
            for (int e = 0; e < 4; e++) oacc[ni][e] = 0.0f;

        const int row0 = qb0 + rb + g;
        const int row1 = row0 + 8;
        const int rmax = qb0 + rb + 15;

        float mrow0, mrow1, lrow0, lrow1;
        unsigned pp[8][2];

        // prologue: S(0) + softmax(0)
        {
            char*  Ksm = Kst;
            float* kmc = kms;
            float scn[8][4];
            #pragma unroll
            for (int ni = 0; ni < 8; ni++)
                #pragma unroll
                for (int e = 0; e < 4; e++) scn[ni][e] = 0.0f;
            #pragma unroll
            for (int ks = 0; ks < 4; ks++) {
                #pragma unroll
                for (int p = 0; p < 4; p++) {
                    unsigned kf[4];
                    int r = p * 16 + b_row;
                    ldm_x4(kf, Ksm + r * 128 + sw8(r, 2 * ks + b_co) * 16);
                    mmabf(scn[2 * p],     qa[ks][0], qa[ks][1], qa[ks][2], qa[ks][3], kf[0], kf[1]);
                    mmabf(scn[2 * p + 1], qa[ks][0], qa[ks][1], qa[ks][2], qa[ks][3], kf[2], kf[3]);
                }
            }
            float kv0 = kmc[lane], kv1 = kmc[lane + 32];
            bool okk = (kv0 != 0.0f) && (kv1 != 0.0f);
            bool allvalid = (__ballot_sync(0xffffffffu, okk) == 0xffffffffu);
            bool interior = (63 <= qb0 + rb);
            float vm0 = -1e30f, vm1 = -1e30f;
            if (interior && allvalid) {
                #pragma unroll
                for (int ni = 0; ni < 8; ni++) {
                    vm0 = fmaxf(vm0, fmaxf(scn[ni][0], scn[ni][1]));
                    vm1 = fmaxf(vm1, fmaxf(scn[ni][2], scn[ni][3]));
                }
            } else {
                #pragma unroll
                for (int ni = 0; ni < 8; ni++) {
                    #pragma unroll
                    for (int e = 0; e < 2; e++) {
                        int cl = ni * 8 + 2 * tig + e;
                        bool km = (kmc[cl] != 0.0f);
                        float v0 = (cl > row0 || !km) ? -1e30f : scn[ni][e];
                        float v1 = (cl > row1 || !km) ? -1e30f : scn[ni][2 + e];
                        scn[ni][e] = v0; scn[ni][2 + e] = v1;
                        vm0 = fmaxf(vm0, v0); vm1 = fmaxf(vm1, v1);
                    }
                }
            }
            vm0 = fmaxf(vm0, __shfl_xor_sync(0xffffffffu, vm0, 1));
            vm0 = fmaxf(vm0, __shfl_xor_sync(0xffffffffu, vm0, 2));
            vm1 = fmaxf(vm1, __shfl_xor_sync(0xffffffffu, vm1, 1));
            vm1 = fmaxf(vm1, __shfl_xor_sync(0xffffffffu, vm1, 2));
            mrow0 = vm0 * CS;
            mrow1 = vm1 * CS;
            float ps0 = 0.0f, ps1 = 0.0f;
            #pragma unroll
            for (int ni = 0; ni < 8; ni++) {
                float p00 = ex2(fmaf(scn[ni][0], CS, -mrow0));
                float p01 = ex2(fmaf(scn[ni][1], CS, -mrow0));
                float p10 = ex2(fmaf(scn[ni][2], CS, -mrow1));
                float p11 = ex2(fmaf(scn[ni][3], CS, -mrow1));
                ps0 += p00 + p01; ps1 += p10 + p11;
                pp[ni][0] = pk2(p00, p01);
                pp[ni][1] = pk2(p10, p11);
            }
            ps0 += __shfl_xor_sync(0xffffffffu, ps0, 1);
            ps0 += __shfl_xor_sync(0xffffffffu, ps0, 2);
            ps1 += __shfl_xor_sync(0xffffffffu, ps1, 1);
            ps1 += __shfl_xor_sync(0xffffffffu, ps1, 2);
            lrow0 = ps0; lrow1 = ps1;
        }

        for (int kt = 0; kt < ntile; kt++) {
            if (kt + 2 < ntile) ld_tile(kt + 2);
            CP_COMMIT();
            CP_WAIT(1);
            __syncthreads();

            if (kt * 64 > rmax) continue;
            char* Vsm = Vst + (kt & 3) * 8192;
            bool activeN = (kt + 1 < ntile) && ((kt + 1) * 64 <= rmax);

            if (activeN) {
                char*  Ksm = Kst + ((kt + 1) & 3) * 8192;
                float* kmc = kms + ((kt + 1) & 3) * 64;
                const int sn0 = (kt + 1) * 64;

                float scn[8][4];
                #pragma unroll
                for (int ni = 0; ni < 8; ni++)
                    #pragma unroll
                    for (int e = 0; e < 4; e++) scn[ni][e] = 0.0f;
                #pragma unroll
                for (int ks = 0; ks < 4; ks++) {
                    #pragma unroll
                    for (int p = 0; p < 4; p++) {
                        unsigned kf[4];
                        int r = p * 16 + b_row;
                        ldm_x4(kf, Ksm + r * 128 + sw8(r, 2 * ks + b_co) * 16);
                        mmabf(scn[2 * p],     qa[ks][0], qa[ks][1], qa[ks][2], qa[ks][3], kf[0], kf[1]);
                        mmabf(scn[2 * p + 1], qa[ks][0], qa[ks][1], qa[ks][2], qa[ks][3], kf[2], kf[3]);
                    }
                }

                float kv0 = kmc[lane], kv1 = kmc[lane + 32];
                bool okk = (kv0 != 0.0f) && (kv1 != 0.0f);
                bool allvalid = (__ballot_sync(0xffffffffu, okk) == 0xffffffffu);
                bool interior = (sn0 + 63 <= qb0 + rb);
                float vm0 = -1e30f, vm1 = -1e30f;
                if (interior && allvalid) {
                    #pragma unroll
                    for (int ni = 0; ni < 8; ni++) {
                        vm0 = fmaxf(vm0, fmaxf(scn[ni][0], scn[ni][1]));
                        vm1 = fmaxf(vm1, fmaxf(scn[ni][2], scn[ni][3]));
                    }
                } else {
                    #pragma unroll
                    for (int ni = 0; ni < 8; ni++) {
                        #pragma unroll
                        for (int e = 0; e < 2; e++) {
                            int cl = ni * 8 + 2 * tig + e;
                            int sg = sn0 + cl;
                            bool km = (kmc[cl] != 0.0f);
                            float v0 = (sg > row0 || !km) ? -1e30f : scn[ni][e];
                            float v1 = (sg > row1 || !km) ? -1e30f : scn[ni][2 + e];
                            scn[ni][e] = v0; scn[ni][2 + e] = v1;
                            vm0 = fmaxf(vm0, v0); vm1 = fmaxf(vm1, v1);
                        }
                    }
                }
                vm0 = fmaxf(vm0, __shfl_xor_sync(0xffffffffu, vm0, 1));
                vm0 = fmaxf(vm0, __shfl_xor_sync(0xffffffffu, vm0, 2));
                vm1 = fmaxf(vm1, __shfl_xor_sync(0xffffffffu, vm1, 1));
                vm1 = fmaxf(vm1, __shfl_xor_sync(0xffffffffu, vm1, 2));
                float mn0 = fmaxf(mrow0, vm0 * CS);
                float mn1 = fmaxf(mrow1, vm1 * CS);

                unsigned ppn[8][2];
                float ps0 = 0.0f, ps1 = 0.0f;
                #pragma unroll
                for (int ni = 0; ni < 8; ni++) {
                    float p00 = ex2(fmaf(scn[ni][0], CS, -mn0));
                    float p01 = ex2(fmaf(scn[ni][1], CS, -mn0));
                    float p10 = ex2(fmaf(scn[ni][2], CS, -mn1));
                    float p11 = ex2(fmaf(scn[ni][3], CS, -mn1));
                    ps0 += p00 + p01; ps1 += p10 + p11;
                    ppn[ni][0] = pk2(p00, p01);
                    ppn[ni][1] = pk2(p10, p11);
                }
                ps0 += __shfl_xor_sync(0xffffffffu, ps0, 1);
                ps0 += __shfl_xor_sync(0xffffffffu, ps0, 2);
                ps1 += __shfl_xor_sync(0xffffffffu, ps1, 1);
                ps1 += __shfl_xor_sync(0xffffffffu, ps1, 2);

                #pragma unroll
                for (int ks = 0; ks < 4; ks++) {
                    unsigned pa0 = pp[2 * ks][0];
                    unsigned pa1 = pp[2 * ks][1];
                    unsigned pa2 = pp[2 * ks + 1][0];
                    unsigned pa3 = pp[2 * ks + 1][1];
                    #pragma unroll
                    for (int p = 0; p < 4; p++) {
                        unsigned vf[4];
                        int r = p * 16 + b_row;
                        ldm_x4(vf, Vsm + r * 128 + sw8(r, 2 * ks + b_co) * 16);
                        mmabf(oacc[2 * p],     pa0, pa1, pa2, pa3, vf[0], vf[1]);
                        mmabf(oacc[2 * p + 1], pa0, pa1, pa2, pa3, vf[2], vf[3]);
                    }
                }

                float al0 = ex2(mrow0 - mn0), al1 = ex2(mrow1 - mn1);
                lrow0 = lrow0 * al0 + ps0;
                lrow1 = lrow1 * al1 + ps1;
                mrow0 = mn0; mrow1 = mn1;
                #pragma unroll
                for (int ni = 0; ni < 8; ni++) {
                    oacc[ni][0] *= al0; oacc[ni][1] *= al0;
                    oacc[ni][2] *= al1; oacc[ni][3] *= al1;
                    pp[ni][0] = ppn[ni][0];
                    pp[ni][1] = ppn[ni][1];
                }
            } else {
                #pragma unroll
                for (int ks = 0; ks < 4; ks++) {
                    unsigned pa0 = pp[2 * ks][0];
                    unsigned pa1 = pp[2 * ks][1];
                    unsigned pa2 = pp[2 * ks + 1][0];
                    unsigned pa3 = pp[2 * ks + 1][1];
                    #pragma unroll
                    for (int p = 0; p < 4; p++) {
                        unsigned vf[4];
                        int r = p * 16 + b_row;
                        ldm_x4(vf, Vsm + r * 128 + sw8(r, 2 * ks + b_co) * 16);
                        mmabf(oacc[2 * p],     pa0, pa1, pa2, pa3, vf[0], vf[1]);
                        mmabf(oacc[2 * p + 1], pa0, pa1, pa2, pa3, vf[2], vf[3]);
                    }
                }
            }
        }

        float qm0 = g_qmask[b * S_ + row0];
        float qm1 = g_qmask[b * S_ + row1];
        float inv0 = qm0 / lrow0;
        float inv1 = qm1 / lrow1;
        #pragma unroll
        for (int ni = 0; ni < 8; ni++) {
            int cc = h * DH_ + ni * 8 + 2 * tig;
            float2 v0, v1;
            v0.x = oacc[ni][0] * inv0; v0.y = oacc[ni][1] * inv0;
            v1.x = oacc[ni][2] * inv1; v1.y = oacc[ni][3] * inv1;
            *(float2*)&g_O[(size_t)(b * S_ + row0) * D_ + cc] = v0;
            *(float2*)&g_O[(size_t)(b * S_ + row1) * D_ + cc] = v1;
        }
    }
}

// ---------------- residual + layernorm ------------------------------------------
__global__ __launch_bounds__(256) void ln_kernel(
    const float* __restrict__ qin, const float* __restrict__ gamma,
    const float* __restrict__ beta, float* __restrict__ out)
{
    __shared__ float red[8];
    __shared__ float red2[8];
    const int row = blockIdx.x;
    const int tid = threadIdx.x;
    size_t base = (size_t)row * D_ + tid * 4;

    float4 o = *(const float4*)&g_O[base];
    float4 q = *(const float4*)&qin[base];
    float x0 = o.x + q.x, x1 = o.y + q.y, x2 = o.z + q.z, x3 = o.w + q.w;

    float s = x0 + x1 + x2 + x3;
    #pragma unroll
    for (int off = 16; off; off >>= 1) s += __shfl_xor_sync(0xffffffffu, s, off);
    if ((tid & 31) == 0) red[tid >> 5] = s;
    __syncthreads();
    float tot = red[0] + red[1] + red[2] + red[3] + red[4] + red[5] + red[6] + red[7];
    float mean = tot * (1.0f / 1024.0f);

    float d0 = x0 - mean, d1 = x1 - mean, d2 = x2 - mean, d3 = x3 - mean;
    float sq = d0 * d0 + d1 * d1 + d2 * d2 + d3 * d3;
    #pragma unroll
    for (int off = 16; off; off >>= 1) sq += __shfl_xor_sync(0xffffffffu, sq, off);
    if ((tid & 31) == 0) red2[tid >> 5] = sq;
    __syncthreads();
    float ssq = red2[0] + red2[1] + red2[2] + red2[3] + red2[4] + red2[5] + red2[6] + red2[7];
    float stdv = sqrtf(ssq / 1023.0f);
    float inv = 1.0f / (stdv + 1e-8f);

    float4 gg = *(const float4*)&gamma[tid * 4];
    float4 be = *(const float4*)&beta[tid * 4];
    float4 y;
    y.x = gg.x * d0 * inv + be.x;
    y.y = gg.y * d1 * inv + be.y;
    y.z = gg.z * d2 * inv + be.z;
    y.w = gg.w * d3 * inv + be.w;
    *(float4*)&out[base] = y;
}

// ---------------- launch -----------------------------------------------------------
extern "C" void kernel_launch(void* const* d_in, const int* in_sizes, int n_in,
                              void* d_out, int out_size)
{
    const float* queries = (const float*)d_in[0];
    const float* keys    = (const float*)d_in[1];
    const float* values  = (const float*)d_in[2];
    const float* Wq      = (const float*)d_in[3];
    const float* bq      = (const float*)d_in[4];
    const float* Wk      = (const float*)d_in[5];
    const float* bk      = (const float*)d_in[6];
    const float* Wv      = (const float*)d_in[7];
    const float* bv      = (const float*)d_in[8];
    const float* gamma   = (const float*)d_in[9];
    const float* beta    = (const float*)d_in[10];
    float* out = (float*)d_out;

    const int proj_smem = NSTG * PSTG;   // 98304 B
    cudaFuncSetAttribute(proj_kernel, cudaFuncAttributeMaxDynamicSharedMemorySize, proj_smem);
    cudaFuncSetAttribute(attn_kernel, cudaFuncAttributeMaxDynamicSharedMemorySize, ATTN_SMEM);

    cvt_kernel<<<dim3(2048, 6), 256>>>(queries, keys, values, Wq, Wk, Wv);
    proj_kernel<<<dim3(8, 32, 3), 256, proj_smem>>>(bq, bk, bv);
    attn_kernel<<<dim3(8, 16, 2), 256, ATTN_SMEM>>>();
    ln_kernel<<<M_, 256>>>(queries, gamma, beta, out);
}

// round 14
// speedup vs baseline: 1.1506x; 1.0323x over previous
#include <cuda_runtime.h>
#include <cuda_bf16.h>
#include <math.h>
#include <cstdint>

#define B_  2
#define S_  2048
#define D_  1024
#define H_  16
#define DH_ 64
#define M_  (B_ * S_)

// ---------------- scratch ----------------------------------------------------
__device__ __nv_bfloat16 g_xq[M_ * D_];
__device__ __nv_bfloat16 g_xk[M_ * D_];
__device__ __nv_bfloat16 g_xv[M_ * D_];
__device__ __nv_bfloat16 g_wq[D_ * D_];
__device__ __nv_bfloat16 g_wk[D_ * D_];
__device__ __nv_bfloat16 g_wv[D_ * D_];
__device__ __nv_bfloat16 g_Q[M_ * D_];
__device__ __nv_bfloat16 g_K[M_ * D_];
__device__ __nv_bfloat16 g_Vt[B_ * H_ * DH_ * S_];
__device__ float g_O[M_ * D_];
__device__ float g_kmask[M_];
__device__ float g_qmask[M_];

// ---------------- helpers ------------------------------------------------------
__device__ __forceinline__ unsigned pk2(float lo, float hi) {
    unsigned r;
    asm("cvt.rn.bf16x2.f32 %0, %1, %2;" : "=r"(r) : "f"(hi), "f"(lo));
    return r;
}
__device__ __forceinline__ float ex2(float x) {
    float y;
    asm("ex2.approx.f32 %0, %1;" : "=f"(y) : "f"(x));
    return y;
}
__device__ __forceinline__ void mmabf(float* c,
                                      unsigned a0, unsigned a1, unsigned a2, unsigned a3,
                                      unsigned b0, unsigned b1) {
    asm volatile(
        "mma.sync.aligned.m16n8k16.row.col.f32.bf16.bf16.f32 "
        "{%0,%1,%2,%3},{%4,%5,%6,%7},{%8,%9},{%0,%1,%2,%3};"
        : "+f"(c[0]), "+f"(c[1]), "+f"(c[2]), "+f"(c[3])
        : "r"(a0), "r"(a1), "r"(a2), "r"(a3), "r"(b0), "r"(b1));
}
__device__ __forceinline__ void cp16(void* smem, const void* gmem) {
    unsigned saddr = (unsigned)__cvta_generic_to_shared(smem);
    asm volatile("cp.async.cg.shared.global [%0], [%1], 16;" :: "r"(saddr), "l"(gmem));
}
#define CP_COMMIT() asm volatile("cp.async.commit_group;")
#define CP_WAIT(N)  asm volatile("cp.async.wait_group %0;" :: "n"(N))
__device__ __forceinline__ int sw8(int row, int c) { return c ^ (row & 7); }
__device__ __forceinline__ void ldm_x4(unsigned* r, const char* p) {
    uint32_t a = (uint32_t)__cvta_generic_to_shared(p);
    asm volatile("ldmatrix.sync.aligned.m8n8.x4.shared.b16 {%0,%1,%2,%3}, [%4];"
        : "=r"(r[0]), "=r"(r[1]), "=r"(r[2]), "=r"(r[3]) : "r"(a));
}

// ---------------- fp32 -> bf16 conversion + row masks ---------------------------
__global__ __launch_bounds__(256) void cvt_kernel(
    const float* __restrict__ q, const float* __restrict__ k, const float* __restrict__ v,
    const float* __restrict__ wq, const float* __restrict__ wk, const float* __restrict__ wv)
{
    __shared__ float rs[8];
    const int z = blockIdx.y;
    const float* src; __nv_bfloat16* dst; int n;
    if (z == 0)      { src = q;  dst = g_xq; n = M_ * D_; }
    else if (z == 1) { src = k;  dst = g_xk; n = M_ * D_; }
    else if (z == 2) { src = v;  dst = g_xv; n = M_ * D_; }
    else if (z == 3) { src = wq; dst = g_wq; n = D_ * D_; }
    else if (z == 4) { src = wk; dst = g_wk; n = D_ * D_; }
    else             { src = wv; dst = g_wv; n = D_ * D_; }

    const int tid = threadIdx.x;
    int base = (blockIdx.x * 256 + tid) * 8;
    if (base >= n) return;
    float4 a = *(const float4*)&src[base];
    float4 b = *(const float4*)&src[base + 4];
    uint4 o;
    o.x = pk2(a.x, a.y); o.y = pk2(a.z, a.w);
    o.z = pk2(b.x, b.y); o.w = pk2(b.z, b.w);
    *(uint4*)&dst[base] = o;

    if (z < 2) {
        float s = a.x + a.y + a.z + a.w + b.x + b.y + b.z + b.w;
        #pragma unroll
        for (int off = 16; off; off >>= 1) s += __shfl_xor_sync(0xffffffffu, s, off);
        if ((tid & 31) == 0) rs[tid >> 5] = s;
        __syncthreads();
        float* msk = (z == 0) ? g_qmask : g_kmask;
        if (tid == 0) {
            float t = rs[0] + rs[1] + rs[2] + rs[3];
            msk[blockIdx.x * 2] = (t != 0.0f) ? 1.0f : 0.0f;
        } else if (tid == 128) {
            float t = rs[4] + rs[5] + rs[6] + rs[7];
            msk[blockIdx.x * 2 + 1] = (t != 0.0f) ? 1.0f : 0.0f;
        }
    }
}

// ---------------- fused QKV projection (64x32 warp tile, BK=64, 3-stage) --------
#define NSTG 3
#define PA_BYTES (128 * 128)
#define PSTG (2 * PA_BYTES)           // 32768
__global__ __launch_bounds__(256) void proj_kernel(
    const float* __restrict__ bq, const float* __restrict__ bk, const float* __restrict__ bv)
{
    extern __shared__ char psm[];

    const __nv_bfloat16* X; const __nv_bfloat16* W; __nv_bfloat16* out; const float* bias;
    if (blockIdx.z == 0)      { X = g_xq; W = g_wq; out = g_Q; bias = bq; }
    else if (blockIdx.z == 1) { X = g_xk; W = g_wk; out = g_K; bias = bk; }
    else                      { X = g_xv; W = g_wv; out = g_Q; bias = bv; }  // out unused z==2

    const int tid  = threadIdx.x;
    const int m0   = blockIdx.y * 128;
    const int n0   = blockIdx.x * 128;
    const int wid  = tid >> 5;
    const int lane = tid & 31;
    const int g    = lane >> 2;
    const int tig  = lane & 3;
    const int wm   = (wid >> 2) * 64;
    const int wn   = (wid & 3) * 32;
    const int sub  = lane >> 3;
    const int rin  = lane & 7;

    const int a_row = (sub & 1) * 8 + rin;
    const int a_co  = sub >> 1;
    const int b_row = (sub >> 1) * 8 + rin;
    const int b_co  = sub & 1;

    float acc[4][4][4];
    #pragma unroll
    for (int i = 0; i < 4; i++)
        #pragma unroll
        for (int j = 0; j < 4; j++)
            #pragma unroll
            for (int e = 0; e < 4; e++) acc[i][j][e] = 0.0f;

    auto load_stage = [&](int stage, int k0) {
        char* As = psm + stage * PSTG;
        char* Bs = As + PA_BYTES;
        #pragma unroll
        for (int lv = 0; lv < 4; lv++) {
            int idx = tid + lv * 256;
            int row = idx >> 3;
            int c   = idx & 7;
            cp16(As + row * 128 + sw8(row, c) * 16, &X[(size_t)(m0 + row) * D_ + k0 + c * 8]);
        }
        #pragma unroll
        for (int lv = 0; lv < 4; lv++) {
            int idx = tid + lv * 256;
            int row = idx >> 3;
            int c   = idx & 7;
            cp16(Bs + row * 128 + sw8(row, c) * 16, &W[(size_t)(n0 + row) * D_ + k0 + c * 8]);
        }
    };

    #pragma unroll
    for (int s = 0; s < NSTG - 1; s++) { load_stage(s, s * 64); CP_COMMIT(); }

    for (int it = 0; it < 16; it++) {
        CP_WAIT(NSTG - 2);
        __syncthreads();
        if (it + NSTG - 1 < 16) load_stage((it + NSTG - 1) % NSTG, (it + NSTG - 1) * 64);
        CP_COMMIT();

        char* As = psm + (it % NSTG) * PSTG;
        char* Bs = As + PA_BYTES;
        #pragma unroll
        for (int ks = 0; ks < 4; ks++) {
            unsigned af[4][4], bf[2][4];
            #pragma unroll
            for (int mi = 0; mi < 4; mi++) {
                int r = wm + mi * 16 + a_row;
                ldm_x4(af[mi], As + r * 128 + sw8(r, 2 * ks + a_co) * 16);
            }
            #pragma unroll
            for (int p = 0; p < 2; p++) {
                int r = wn + p * 16 + b_row;
                ldm_x4(bf[p], Bs + r * 128 + sw8(r, 2 * ks + b_co) * 16);
            }
            #pragma unroll
            for (int mi = 0; mi < 4; mi++)
                #pragma unroll
                for (int ni = 0; ni < 4; ni++)
                    mmabf(acc[mi][ni], af[mi][0], af[mi][1], af[mi][2], af[mi][3],
                          bf[ni >> 1][(ni & 1) * 2], bf[ni >> 1][(ni & 1) * 2 + 1]);
        }
    }

    if (blockIdx.z != 2) {
        #pragma unroll
        for (int mi = 0; mi < 4; mi++) {
            int r0 = m0 + wm + mi * 16 + g;
            #pragma unroll
            for (int ni = 0; ni < 4; ni++) {
                int cc = n0 + wn + ni * 8 + 2 * tig;
                float bb0 = bias[cc], bb1 = bias[cc + 1];
                *(unsigned*)&out[(size_t)r0 * D_ + cc] =
                    pk2(fmaxf(acc[mi][ni][0] + bb0, 0.0f), fmaxf(acc[mi][ni][1] + bb1, 0.0f));
                *(unsigned*)&out[(size_t)(r0 + 8) * D_ + cc] =
                    pk2(fmaxf(acc[mi][ni][2] + bb0, 0.0f), fmaxf(acc[mi][ni][3] + bb1, 0.0f));
            }
        }
    } else {
        __syncthreads();
        unsigned* stage = (unsigned*)psm;
        #pragma unroll
        for (int mi = 0; mi < 4; mi++) {
            int rl = wm + mi * 16 + g;
            #pragma unroll
            for (int ni = 0; ni < 4; ni++) {
                int ccl = wn + ni * 8 + 2 * tig;
                float bb0 = bias[n0 + ccl], bb1 = bias[n0 + ccl + 1];
                stage[rl * 68 + ccl / 2] =
                    pk2(fmaxf(acc[mi][ni][0] + bb0, 0.0f), fmaxf(acc[mi][ni][1] + bb1, 0.0f));
                stage[(rl + 8) * 68 + ccl / 2] =
                    pk2(fmaxf(acc[mi][ni][2] + bb0, 0.0f), fmaxf(acc[mi][ni][3] + bb1, 0.0f));
            }
        }
        __syncthreads();
        const int bb = m0 >> 11;
        const int s0 = m0 & 2047;
        #pragma unroll
        for (int i = 0; i < 8; i++) {
            int idx = tid + i * 256;
            int c   = idx & 127;
            int rg  = idx >> 7;
            int r0r = rg * 8;
            int h   = (n0 + c) >> 6;
            int d   = (n0 + c) & 63;
            unsigned sel = (c & 1) ? 0x7632u : 0x5410u;
            uint4 o;
            unsigned* po = (unsigned*)&o;
            #pragma unroll
            for (int j = 0; j < 4; j++) {
                unsigned w0 = stage[(r0r + 2 * j)     * 68 + (c >> 1)];
                unsigned w1 = stage[(r0r + 2 * j + 1) * 68 + (c >> 1)];
                asm("prmt.b32 %0, %1, %2, %3;" : "=r"(po[j]) : "r"(w0), "r"(w1), "r"(sel));
            }
            *(uint4*)&g_Vt[(size_t)((bb * H_ + h) * DH_ + d) * S_ + s0 + r0r] = o;
        }
    }
}

// ---------------- causal flash attention (bin-packed q-tiles, 288 blocks) -------
// blockIdx.x -> q-tile bin: {15}, {14}, {13,0}, {12,1}, ..., {7,6}.
// Bin costs: 17,16,17,...,17 tile-units -> one uniform wave on 296 CTA slots.
#define AKQ 16384
#define AKV (AKQ + 4 * 8192)
#define AKM (AKV + 4 * 8192)
#define ATTN_SMEM (AKM + 4 * 256)
#define CS 0.1803368801f   // 0.125 * log2(e)
__global__ __launch_bounds__(256) void attn_kernel()
{
    extern __shared__ char sm[];
    char*  qp  = sm;
    char*  Kst = sm + AKQ;
    char*  Vst = sm + AKV;
    float* kms = (float*)(sm + AKM);

    const int h    = blockIdx.y;
    const int b    = blockIdx.z;
    const int tid  = threadIdx.x;
    const int lane = tid & 31;
    const int wid  = tid >> 5;
    const int g    = lane >> 2;
    const int tig  = lane & 3;
    const int rb   = wid * 16;
    const int sub  = lane >> 3;
    const int rin  = lane & 7;

    const int a_row = (sub & 1) * 8 + rin;
    const int a_co  = sub >> 1;
    const int b_row = (sub >> 1) * 8 + rin;
    const int b_co  = sub & 1;

    // q-tile bin assignment
    int qlist[2];
    int nq;
    {
        int i = blockIdx.x;
        if (i == 0)      { qlist[0] = 15; nq = 1; }
        else if (i == 1) { qlist[0] = 14; nq = 1; }
        else             { qlist[0] = 15 - i; qlist[1] = i - 2; nq = 2; }
    }

    const __nv_bfloat16* Vtg = g_Vt + (size_t)(b * H_ + h) * DH_ * S_;

    auto ld_tile = [&](int t) {
        char* Ks = Kst + (t & 3) * 8192;
        char* Vs = Vst + (t & 3) * 8192;
        int sn = t * 64;
        #pragma unroll
        for (int lv = 0; lv < 2; lv++) {
            int idx = tid + lv * 256;
            int r = idx >> 3;
            int c = idx & 7;
            cp16(Ks + r * 128 + sw8(r, c) * 16,
                 &g_K[(size_t)(b * S_ + sn + r) * D_ + h * DH_ + c * 8]);
            cp16(Vs + r * 128 + sw8(r, c) * 16, &Vtg[(size_t)r * S_ + sn + c * 8]);
        }
        if (tid < 16) cp16(&kms[(t & 3) * 64 + tid * 4], &g_kmask[b * S_ + sn + tid * 4]);
    };

    #pragma unroll 1
    for (int half = 0; half < nq; half++) {
        const int qt  = qlist[half];
        const int qb0 = qt * 128;
        const int ntile = (qb0 >> 6) + 2;

        __syncthreads();

        #pragma unroll
        for (int lv = 0; lv < 4; lv++) {
            int idx = tid + lv * 256;
            int r = idx >> 3;
            int c = idx & 7;
            cp16(qp + r * 128 + sw8(r, c) * 16,
                 &g_Q[(size_t)(b * S_ + qb0 + r) * D_ + h * DH_ + c * 8]);
        }
        CP_COMMIT();
        ld_tile(0); CP_COMMIT();
        ld_tile(1); CP_COMMIT();

        CP_WAIT(1);
        __syncthreads();

        unsigned qa[4][4];
        #pragma unroll
        for (int ks = 0; ks < 4; ks++) {
            int r = rb + a_row;
            ldm_x4(qa[ks], qp + r * 128 + sw8(r, 2 * ks + a_co) * 16);
        }

        float oacc[8][4];
        #pragma unroll
        for (int ni = 0; ni < 8; ni++)
            #pragma unroll
            for (int e = 0; e < 4; e++) oacc[ni][e] = 0.0f;

        const int row0 = qb0 + rb + g;
        const int row1 = row0 + 8;
        const int rmax = qb0 + rb + 15;

        float mrow0, mrow1, lrow0, lrow1;
        unsigned pp[8][2];

        // prologue: S(0) + softmax(0)
        {
            char*  Ksm = Kst;
            float* kmc = kms;
            float scn[8][4];
            #pragma unroll
            for (int ni = 0; ni < 8; ni++)
                #pragma unroll
                for (int e = 0; e < 4; e++) scn[ni][e] = 0.0f;
            #pragma unroll
            for (int ks = 0; ks < 4; ks++) {
                #pragma unroll
                for (int p = 0; p < 4; p++) {
                    unsigned kf[4];
                    int r = p * 16 + b_row;
                    ldm_x4(kf, Ksm + r * 128 + sw8(r, 2 * ks + b_co) * 16);
                    mmabf(scn[2 * p],     qa[ks][0], qa[ks][1], qa[ks][2], qa[ks][3], kf[0], kf[1]);
                    mmabf(scn[2 * p + 1], qa[ks][0], qa[ks][1], qa[ks][2], qa[ks][3], kf[2], kf[3]);
                }
            }
            float kv0 = kmc[lane], kv1 = kmc[lane + 32];
            bool okk = (kv0 != 0.0f) && (kv1 != 0.0f);
            bool allvalid = (__ballot_sync(0xffffffffu, okk) == 0xffffffffu);
            bool interior = (63 <= qb0 + rb);
            float vm0 = -1e30f, vm1 = -1e30f;
            if (interior && allvalid) {
                #pragma unroll
                for (int ni = 0; ni < 8; ni++) {
                    vm0 = fmaxf(vm0, fmaxf(scn[ni][0], scn[ni][1]));
                    vm1 = fmaxf(vm1, fmaxf(scn[ni][2], scn[ni][3]));
                }
            } else {
                #pragma unroll
                for (int ni = 0; ni < 8; ni++) {
                    #pragma unroll
                    for (int e = 0; e < 2; e++) {
                        int cl = ni * 8 + 2 * tig + e;
                        bool km = (kmc[cl] != 0.0f);
                        float v0 = (cl > row0 || !km) ? -1e30f : scn[ni][e];
                        float v1 = (cl > row1 || !km) ? -1e30f : scn[ni][2 + e];
                        scn[ni][e] = v0; scn[ni][2 + e] = v1;
                        vm0 = fmaxf(vm0, v0); vm1 = fmaxf(vm1, v1);
                    }
                }
            }
            vm0 = fmaxf(vm0, __shfl_xor_sync(0xffffffffu, vm0, 1));
            vm0 = fmaxf(vm0, __shfl_xor_sync(0xffffffffu, vm0, 2));
            vm1 = fmaxf(vm1, __shfl_xor_sync(0xffffffffu, vm1, 1));
            vm1 = fmaxf(vm1, __shfl_xor_sync(0xffffffffu, vm1, 2));
            mrow0 = vm0 * CS;
            mrow1 = vm1 * CS;
            float ps0 = 0.0f, ps1 = 0.0f;
            #pragma unroll
            for (int ni = 0; ni < 8; ni++) {
                float p00 = ex2(fmaf(scn[ni][0], CS, -mrow0));
                float p01 = ex2(fmaf(scn[ni][1], CS, -mrow0));
                float p10 = ex2(fmaf(scn[ni][2], CS, -mrow1));
                float p11 = ex2(fmaf(scn[ni][3], CS, -mrow1));
                ps0 += p00 + p01; ps1 += p10 + p11;
                pp[ni][0] = pk2(p00, p01);
                pp[ni][1] = pk2(p10, p11);
            }
            ps0 += __shfl_xor_sync(0xffffffffu, ps0, 1);
            ps0 += __shfl_xor_sync(0xffffffffu, ps0, 2);
            ps1 += __shfl_xor_sync(0xffffffffu, ps1, 1);
            ps1 += __shfl_xor_sync(0xffffffffu, ps1, 2);
            lrow0 = ps0; lrow1 = ps1;
        }

        for (int kt = 0; kt < ntile; kt++) {
            if (kt + 2 < ntile) ld_tile(kt + 2);
            CP_COMMIT();
            CP_WAIT(1);
            __syncthreads();

            if (kt * 64 > rmax) continue;
            char* Vsm = Vst + (kt & 3) * 8192;
            bool activeN = (kt + 1 < ntile) && ((kt + 1) * 64 <= rmax);

            if (activeN) {
                char*  Ksm = Kst + ((kt + 1) & 3) * 8192;
                float* kmc = kms + ((kt + 1) & 3) * 64;
                const int sn0 = (kt + 1) * 64;

                float scn[8][4];
                #pragma unroll
                for (int ni = 0; ni < 8; ni++)
                    #pragma unroll
                    for (int e = 0; e < 4; e++) scn[ni][e] = 0.0f;
                #pragma unroll
                for (int ks = 0; ks < 4; ks++) {
                    #pragma unroll
                    for (int p = 0; p < 4; p++) {
                        unsigned kf[4];
                        int r = p * 16 + b_row;
                        ldm_x4(kf, Ksm + r * 128 + sw8(r, 2 * ks + b_co) * 16);
                        mmabf(scn[2 * p],     qa[ks][0], qa[ks][1], qa[ks][2], qa[ks][3], kf[0], kf[1]);
                        mmabf(scn[2 * p + 1], qa[ks][0], qa[ks][1], qa[ks][2], qa[ks][3], kf[2], kf[3]);
                    }
                }

                float kv0 = kmc[lane], kv1 = kmc[lane + 32];
                bool okk = (kv0 != 0.0f) && (kv1 != 0.0f);
                bool allvalid = (__ballot_sync(0xffffffffu, okk) == 0xffffffffu);
                bool interior = (sn0 + 63 <= qb0 + rb);
                float vm0 = -1e30f, vm1 = -1e30f;
                if (interior && allvalid) {
                    #pragma unroll
                    for (int ni = 0; ni < 8; ni++) {
                        vm0 = fmaxf(vm0, fmaxf(scn[ni][0], scn[ni][1]));
                        vm1 = fmaxf(vm1, fmaxf(scn[ni][2], scn[ni][3]));
                    }
                } else {
                    #pragma unroll
                    for (int ni = 0; ni < 8; ni++) {
                        #pragma unroll
                        for (int e = 0; e < 2; e++) {
                            int cl = ni * 8 + 2 * tig + e;
                            int sg = sn0 + cl;
                            bool km = (kmc[cl] != 0.0f);
                            float v0 = (sg > row0 || !km) ? -1e30f : scn[ni][e];
                            float v1 = (sg > row1 || !km) ? -1e30f : scn[ni][2 + e];
                            scn[ni][e] = v0; scn[ni][2 + e] = v1;
                            vm0 = fmaxf(vm0, v0); vm1 = fmaxf(vm1, v1);
                        }
                    }
                }
                vm0 = fmaxf(vm0, __shfl_xor_sync(0xffffffffu, vm0, 1));
                vm0 = fmaxf(vm0, __shfl_xor_sync(0xffffffffu, vm0, 2));
                vm1 = fmaxf(vm1, __shfl_xor_sync(0xffffffffu, vm1, 1));
                vm1 = fmaxf(vm1, __shfl_xor_sync(0xffffffffu, vm1, 2));
                float mn0 = fmaxf(mrow0, vm0 * CS);
                float mn1 = fmaxf(mrow1, vm1 * CS);

                unsigned ppn[8][2];
                float ps0 = 0.0f, ps1 = 0.0f;
                #pragma unroll
                for (int ni = 0; ni < 8; ni++) {
                    float p00 = ex2(fmaf(scn[ni][0], CS, -mn0));
                    float p01 = ex2(fmaf(scn[ni][1], CS, -mn0));
                    float p10 = ex2(fmaf(scn[ni][2], CS, -mn1));
                    float p11 = ex2(fmaf(scn[ni][3], CS, -mn1));
                    ps0 += p00 + p01; ps1 += p10 + p11;
                    ppn[ni][0] = pk2(p00, p01);
                    ppn[ni][1] = pk2(p10, p11);
                }
                ps0 += __shfl_xor_sync(0xffffffffu, ps0, 1);
                ps0 += __shfl_xor_sync(0xffffffffu, ps0, 2);
                ps1 += __shfl_xor_sync(0xffffffffu, ps1, 1);
                ps1 += __shfl_xor_sync(0xffffffffu, ps1, 2);

                #pragma unroll
                for (int ks = 0; ks < 4; ks++) {
                    unsigned pa0 = pp[2 * ks][0];
                    unsigned pa1 = pp[2 * ks][1];
                    unsigned pa2 = pp[2 * ks + 1][0];
                    unsigned pa3 = pp[2 * ks + 1][1];
                    #pragma unroll
                    for (int p = 0; p < 4; p++) {
                        unsigned vf[4];
                        int r = p * 16 + b_row;
                        ldm_x4(vf, Vsm + r * 128 + sw8(r, 2 * ks + b_co) * 16);
                        mmabf(oacc[2 * p],     pa0, pa1, pa2, pa3, vf[0], vf[1]);
                        mmabf(oacc[2 * p + 1], pa0, pa1, pa2, pa3, vf[2], vf[3]);
                    }
                }

                float al0 = ex2(mrow0 - mn0), al1 = ex2(mrow1 - mn1);
                lrow0 = lrow0 * al0 + ps0;
                lrow1 = lrow1 * al1 + ps1;
                mrow0 = mn0; mrow1 = mn1;
                #pragma unroll
                for (int ni = 0; ni < 8; ni++) {
                    oacc[ni][0] *= al0; oacc[ni][1] *= al0;
                    oacc[ni][2] *= al1; oacc[ni][3] *= al1;
                    pp[ni][0] = ppn[ni][0];
                    pp[ni][1] = ppn[ni][1];
                }
            } else {
                #pragma unroll
                for (int ks = 0; ks < 4; ks++) {
                    unsigned pa0 = pp[2 * ks][0];
                    unsigned pa1 = pp[2 * ks][1];
                    unsigned pa2 = pp[2 * ks + 1][0];
                    unsigned pa3 = pp[2 * ks + 1][1];
                    #pragma unroll
                    for (int p = 0; p < 4; p++) {
                        unsigned vf[4];
                        int r = p * 16 + b_row;
                        ldm_x4(vf, Vsm + r * 128 + sw8(r, 2 * ks + b_co) * 16);
                        mmabf(oacc[2 * p],     pa0, pa1, pa2, pa3, vf[0], vf[1]);
                        mmabf(oacc[2 * p + 1], pa0, pa1, pa2, pa3, vf[2], vf[3]);
                    }
                }
            }
        }

        float qm0 = g_qmask[b * S_ + row0];
        float qm1 = g_qmask[b * S_ + row1];
        float inv0 = qm0 / lrow0;
        float inv1 = qm1 / lrow1;
        #pragma unroll
        for (int ni = 0; ni < 8; ni++) {
            int cc = h * DH_ + ni * 8 + 2 * tig;
            float2 v0, v1;
            v0.x = oacc[ni][0] * inv0; v0.y = oacc[ni][1] * inv0;
            v1.x = oacc[ni][2] * inv1; v1.y = oacc[ni][3] * inv1;
            *(float2*)&g_O[(size_t)(b * S_ + row0) * D_ + cc] = v0;
            *(float2*)&g_O[(size_t)(b * S_ + row1) * D_ + cc] = v1;
        }
    }
}

// ---------------- residual + layernorm ------------------------------------------
__global__ __launch_bounds__(256) void ln_kernel(
    const float* __restrict__ qin, const float* __restrict__ gamma,
    const float* __restrict__ beta, float* __restrict__ out)
{
    __shared__ float red[8];
    __shared__ float red2[8];
    const int row = blockIdx.x;
    const int tid = threadIdx.x;
    size_t base = (size_t)row * D_ + tid * 4;

    float4 o = *(const float4*)&g_O[base];
    float4 q = *(const float4*)&qin[base];
    float x0 = o.x + q.x, x1 = o.y + q.y, x2 = o.z + q.z, x3 = o.w + q.w;

    float s = x0 + x1 + x2 + x3;
    #pragma unroll
    for (int off = 16; off; off >>= 1) s += __shfl_xor_sync(0xffffffffu, s, off);
    if ((tid & 31) == 0) red[tid >> 5] = s;
    __syncthreads();
    float tot = red[0] + red[1] + red[2] + red[3] + red[4] + red[5] + red[6] + red[7];
    float mean = tot * (1.0f / 1024.0f);

    float d0 = x0 - mean, d1 = x1 - mean, d2 = x2 - mean, d3 = x3 - mean;
    float sq = d0 * d0 + d1 * d1 + d2 * d2 + d3 * d3;
    #pragma unroll
    for (int off = 16; off; off >>= 1) sq += __shfl_xor_sync(0xffffffffu, sq, off);
    if ((tid & 31) == 0) red2[tid >> 5] = sq;
    __syncthreads();
    float ssq = red2[0] + red2[1] + red2[2] + red2[3] + red2[4] + red2[5] + red2[6] + red2[7];
    float stdv = sqrtf(ssq / 1023.0f);
    float inv = 1.0f / (stdv + 1e-8f);

    float4 gg = *(const float4*)&gamma[tid * 4];
    float4 be = *(const float4*)&beta[tid * 4];
    float4 y;
    y.x = gg.x * d0 * inv + be.x;
    y.y = gg.y * d1 * inv + be.y;
    y.z = gg.z * d2 * inv + be.z;
    y.w = gg.w * d3 * inv + be.w;
    *(float4*)&out[base] = y;
}

// ---------------- launch -----------------------------------------------------------
extern "C" void kernel_launch(void* const* d_in, const int* in_sizes, int n_in,
                              void* d_out, int out_size)
{
    const float* queries = (const float*)d_in[0];
    const float* keys    = (const float*)d_in[1];
    const float* values  = (const float*)d_in[2];
    const float* Wq      = (const float*)d_in[3];
    const float* bq      = (const float*)d_in[4];
    const float* Wk      = (const float*)d_in[5];
    const float* bk      = (const float*)d_in[6];
    const float* Wv      = (const float*)d_in[7];
    const float* bv      = (const float*)d_in[8];
    const float* gamma   = (const float*)d_in[9];
    const float* beta    = (const float*)d_in[10];
    float* out = (float*)d_out;

    const int proj_smem = NSTG * PSTG;   // 98304 B
    cudaFuncSetAttribute(proj_kernel, cudaFuncAttributeMaxDynamicSharedMemorySize, proj_smem);
    cudaFuncSetAttribute(attn_kernel, cudaFuncAttributeMaxDynamicSharedMemorySize, ATTN_SMEM);

    cvt_kernel<<<dim3(2048, 6), 256>>>(queries, keys, values, Wq, Wk, Wv);
    proj_kernel<<<dim3(8, 32, 3), 256, proj_smem>>>(bq, bk, bv);
    attn_kernel<<<dim3(9, 16, 2), 256, ATTN_SMEM>>>();
    ln_kernel<<<M_, 256>>>(queries, gamma, beta, out);
}